// round 1
// baseline (speedup 1.0000x reference)
#include <cuda_runtime.h>
#include <math.h>
#include <stdint.h>

// Problem constants
constexpr int BB = 2048;   // batch
constexpr int TT = 64;     // time steps
constexpr int SS = 64;     // state dim
constexpr int AA = 16;     // action dim
constexpr int HH = 512;    // hidden
constexpr int RR = 512;    // belief dim
constexpr int EE = 1024;   // obs embedding dim

// ---------------- device scratch (no allocations allowed) ----------------
__device__ float g_x   [BB * HH];          // elu(cat(post,a) @ W_as + b)
__device__ float g_gi  [BB * 3 * RR];
__device__ float g_gh  [BB * 3 * RR];
__device__ float g_bel [BB * RR];          // recurrent belief state
__device__ float g_post[BB * SS];          // recurrent posterior state
__device__ float g_h1  [BB * HH];
__device__ float g_h2  [BB * HH];
__device__ float g_p   [BB * 2 * SS];
__device__ float g_q   [BB * 2 * SS];
__device__ float g_qpre[(size_t)BB * TT * HH];   // obs @ W_q1[R:,:] + b_q1 (256MB)
__device__ float g_Wih_t[HH * 3 * RR];     // W_ih transposed -> [512,1536]
__device__ float g_Whh_t[RR * 3 * RR];     // W_hh transposed -> [512,1536]

// ---------------- generic fp32 GEMM with fused epilogue ----------------
// C[M,N] = act( [A1|A2][M,K] @ W[K,N] + bias + add ), all row-major.
// A is the column-concat of A1 (first K1 cols) and A2; K1 % BK == 0 required.
// act: 0 = none, 1 = ELU
template<int BM, int BN, int BK, int TM, int TN>
__global__ __launch_bounds__(256)
void gemm_kernel(const float* __restrict__ A1, int lda1, int K1,
                 const float* __restrict__ A2, int lda2, int K,
                 const float* __restrict__ W, int N,
                 const float* __restrict__ bias,
                 const float* __restrict__ add, int ldadd,
                 float* __restrict__ C, int act)
{
    __shared__ float As[BK][BM];
    __shared__ float Bs[BK][BN];

    const int tid = threadIdx.x;
    const int tx = tid % (BN / TN);          // column group
    const int ty = tid / (BN / TN);          // row group
    const int m0 = blockIdx.y * BM;
    const int n0 = blockIdx.x * BN;

    float acc[TM][TN];
#pragma unroll
    for (int i = 0; i < TM; i++)
#pragma unroll
        for (int j = 0; j < TN; j++) acc[i][j] = 0.f;

    const int ktiles = K / BK;
    for (int kt = 0; kt < ktiles; ++kt) {
        const int k0 = kt * BK;
        const float* Asrc; int lda, ko;
        if (k0 < K1) { Asrc = A1; lda = lda1; ko = k0; }
        else         { Asrc = A2; lda = lda2; ko = k0 - K1; }

        // load A tile (BM x BK) as float4, store transposed into As
        constexpr int AV = BM * BK / 4;       // float4 elements
#pragma unroll
        for (int it = 0; it < AV / 256; ++it) {
            int idx = tid + it * 256;
            int row = idx / (BK / 4);
            int kc  = idx % (BK / 4);
            float4 v = *reinterpret_cast<const float4*>(
                &Asrc[(size_t)(m0 + row) * lda + ko + kc * 4]);
            As[kc * 4 + 0][row] = v.x;
            As[kc * 4 + 1][row] = v.y;
            As[kc * 4 + 2][row] = v.z;
            As[kc * 4 + 3][row] = v.w;
        }
        // load B tile (BK x BN)
        constexpr int BV = BK * BN / 4;
#pragma unroll
        for (int it = 0; it < BV / 256; ++it) {
            int idx = tid + it * 256;
            int kr = idx / (BN / 4);
            int nc = idx % (BN / 4);
            *reinterpret_cast<float4*>(&Bs[kr][nc * 4]) =
                *reinterpret_cast<const float4*>(
                    &W[(size_t)(k0 + kr) * N + n0 + nc * 4]);
        }
        __syncthreads();

#pragma unroll
        for (int kk = 0; kk < BK; ++kk) {
            float a[TM], b[TN];
#pragma unroll
            for (int i = 0; i < TM; i++) a[i] = As[kk][ty * TM + i];
#pragma unroll
            for (int j = 0; j < TN; j++) b[j] = Bs[kk][tx * TN + j];
#pragma unroll
            for (int i = 0; i < TM; i++)
#pragma unroll
                for (int j = 0; j < TN; j++) acc[i][j] += a[i] * b[j];
        }
        __syncthreads();
    }

    // epilogue (TN must be 4)
    const int colb = n0 + tx * TN;
    float4 bb = make_float4(0.f, 0.f, 0.f, 0.f);
    if (bias) bb = *reinterpret_cast<const float4*>(&bias[colb]);
#pragma unroll
    for (int i = 0; i < TM; i++) {
        size_t row = (size_t)(m0 + ty * TM + i);
        float4 v = make_float4(acc[i][0] + bb.x, acc[i][1] + bb.y,
                               acc[i][2] + bb.z, acc[i][3] + bb.w);
        if (add) {
            float4 aa = *reinterpret_cast<const float4*>(&add[row * ldadd + colb]);
            v.x += aa.x; v.y += aa.y; v.z += aa.z; v.w += aa.w;
        }
        if (act == 1) {
            v.x = v.x > 0.f ? v.x : expm1f(v.x);
            v.y = v.y > 0.f ? v.y : expm1f(v.y);
            v.z = v.z > 0.f ? v.z : expm1f(v.z);
            v.w = v.w > 0.f ? v.w : expm1f(v.w);
        }
        *reinterpret_cast<float4*>(&C[row * N + colb]) = v;
    }
}

// ---------------- transpose [rows,cols] -> [cols,rows] ----------------
__global__ void transpose_kernel(const float* __restrict__ in, float* __restrict__ out,
                                 int rows, int cols)
{
    __shared__ float tile[32][33];
    const int c0 = blockIdx.x * 32, r0 = blockIdx.y * 32;
    const int tx = threadIdx.x, ty = threadIdx.y;   // 32 x 8
#pragma unroll
    for (int y = 0; y < 32; y += 8)
        tile[ty + y][tx] = in[(size_t)(r0 + ty + y) * cols + c0 + tx];
    __syncthreads();
#pragma unroll
    for (int y = 0; y < 32; y += 8)
        out[(size_t)(c0 + ty + y) * rows + r0 + tx] = tile[tx][ty + y];
}

// ---------------- elementwise kernels ----------------
__global__ void copy_kernel(float* __restrict__ dst, const float* __restrict__ src, int n)
{
    int i = blockIdx.x * blockDim.x + threadIdx.x;
    if (i < n) dst[i] = src[i];
}

__device__ __forceinline__ float sigmoidf_(float x) { return 1.f / (1.f + expf(-x)); }

__global__ void gru_kernel(float* __restrict__ out_bel, int t)
{
    int idx = blockIdx.x * blockDim.x + threadIdx.x;
    if (idx >= BB * RR) return;
    int b = idx >> 9, r = idx & 511;
    const float* gi = g_gi + (size_t)b * (3 * RR);
    const float* gh = g_gh + (size_t)b * (3 * RR);
    float ir = gi[r], iz = gi[RR + r], in = gi[2 * RR + r];
    float hr = gh[r], hz = gh[RR + r], hn = gh[2 * RR + r];
    float bo = g_bel[idx];
    float rg = sigmoidf_(ir + hr);
    float zg = sigmoidf_(iz + hz);
    float nn = tanhf(in + rg * hn);
    float bn = (1.f - zg) * nn + zg * bo;
    g_bel[idx] = bn;
    out_bel[((size_t)b * TT + t) * RR + r] = bn;
}

// pq: [B, 2S] -> mean/std/state outputs at step t. state_buf != null => also
// update the recurrent posterior state.
__global__ void dist_kernel(const float* __restrict__ pq, const float* __restrict__ noise,
                            float* __restrict__ o_mean, float* __restrict__ o_std,
                            float* __restrict__ o_state, float* __restrict__ state_buf, int t)
{
    int idx = blockIdx.x * blockDim.x + threadIdx.x;
    if (idx >= BB * SS) return;
    int b = idx >> 6, s = idx & 63;
    float m   = pq[(size_t)b * (2 * SS) + s];
    float raw = pq[(size_t)b * (2 * SS) + SS + s];
    float sp = raw > 20.f ? raw : log1pf(expf(raw));
    float sd = sp + 0.1f;
    float eps = noise[((size_t)b * TT + t) * SS + s];
    float st = m + sd * eps;
    size_t o = ((size_t)b * TT + t) * SS + s;
    o_mean[o] = m; o_std[o] = sd; o_state[o] = st;
    if (state_buf) state_buf[idx] = st;
}

// ---------------- launch ----------------
extern "C" void kernel_launch(void* const* d_in, const int* in_sizes, int n_in,
                              void* d_out, int out_size)
{
    const float* posterior = (const float*)d_in[0];
    const float* belief    = (const float*)d_in[1];
    const float* actions   = (const float*)d_in[2];
    const float* obs       = (const float*)d_in[3];
    const float* noise_p   = (const float*)d_in[4];
    const float* noise_q   = (const float*)d_in[5];
    const float* W_as = (const float*)d_in[6];
    const float* b_as = (const float*)d_in[7];
    const float* W_ih = (const float*)d_in[8];
    const float* b_ih = (const float*)d_in[9];
    const float* W_hh = (const float*)d_in[10];
    const float* b_hh = (const float*)d_in[11];
    const float* W_p1 = (const float*)d_in[12];
    const float* b_p1 = (const float*)d_in[13];
    const float* W_p2 = (const float*)d_in[14];
    const float* b_p2 = (const float*)d_in[15];
    const float* W_q1 = (const float*)d_in[16];
    const float* b_q1 = (const float*)d_in[17];
    const float* W_q2 = (const float*)d_in[18];
    const float* b_q2 = (const float*)d_in[19];

    float *px, *pgi, *pgh, *pbel, *ppost, *ph1, *ph2, *pp, *pq, *pqpre, *pWih, *pWhh;
    cudaGetSymbolAddress((void**)&px,    g_x);
    cudaGetSymbolAddress((void**)&pgi,   g_gi);
    cudaGetSymbolAddress((void**)&pgh,   g_gh);
    cudaGetSymbolAddress((void**)&pbel,  g_bel);
    cudaGetSymbolAddress((void**)&ppost, g_post);
    cudaGetSymbolAddress((void**)&ph1,   g_h1);
    cudaGetSymbolAddress((void**)&ph2,   g_h2);
    cudaGetSymbolAddress((void**)&pp,    g_p);
    cudaGetSymbolAddress((void**)&pq,    g_q);
    cudaGetSymbolAddress((void**)&pqpre, g_qpre);
    cudaGetSymbolAddress((void**)&pWih,  g_Wih_t);
    cudaGetSymbolAddress((void**)&pWhh,  g_Whh_t);

    float* out = (float*)d_out;
    const size_t BT = (size_t)BB * TT;
    float* o_pmean = out;
    float* o_pstd  = out + BT * SS;
    float* o_prior = out + 2 * BT * SS;
    float* o_bel   = out + 3 * BT * SS;
    float* o_qmean = out + 3 * BT * SS + BT * RR;
    float* o_qstd  = o_qmean + BT * SS;
    float* o_post  = o_qstd  + BT * SS;

    // init recurrent state
    copy_kernel<<<(BB * RR + 255) / 256, 256>>>(pbel, belief, BB * RR);
    copy_kernel<<<(BB * SS + 255) / 256, 256>>>(ppost, posterior, BB * SS);

    // pre-transpose GRU weights: [3R, H] -> [H, 3R]
    transpose_kernel<<<dim3(HH / 32, 3 * RR / 32), dim3(32, 8)>>>(W_ih, pWih, 3 * RR, HH);
    transpose_kernel<<<dim3(RR / 32, 3 * RR / 32), dim3(32, 8)>>>(W_hh, pWhh, 3 * RR, RR);

    // precompute obs contribution to q1 for ALL timesteps:
    // g_qpre[b,t,:] = obs[b,t,:] @ W_q1[R:R+E, :] + b_q1
    gemm_kernel<128, 64, 16, 8, 4><<<dim3(HH / 64, (BB * TT) / 128), 256>>>(
        obs, EE, EE, nullptr, 0, EE,
        W_q1 + (size_t)RR * HH, HH, b_q1, nullptr, 0, pqpre, 0);

    for (int t = 0; t < TT; ++t) {
        // x = elu(cat(post_s, a_t) @ W_as + b_as)          [B,512], K=80
        gemm_kernel<128, 64, 16, 8, 4><<<dim3(HH / 64, BB / 128), 256>>>(
            ppost, SS, SS, actions + (size_t)t * AA, TT * AA, SS + AA,
            W_as, HH, b_as, nullptr, 0, px, 1);
        // gi = x @ W_ih^T + b_ih                           [B,1536]
        gemm_kernel<128, 64, 16, 8, 4><<<dim3(3 * RR / 64, BB / 128), 256>>>(
            px, HH, HH, nullptr, 0, HH,
            pWih, 3 * RR, b_ih, nullptr, 0, pgi, 0);
        // gh = bel @ W_hh^T + b_hh                         [B,1536]
        gemm_kernel<128, 64, 16, 8, 4><<<dim3(3 * RR / 64, BB / 128), 256>>>(
            pbel, RR, RR, nullptr, 0, RR,
            pWhh, 3 * RR, b_hh, nullptr, 0, pgh, 0);
        // GRU gates -> bel_new (in place) + output slice
        gru_kernel<<<(BB * RR) / 256, 256>>>(o_bel, t);
        // prior head: h1 = elu(bel @ W_p1 + b_p1)
        gemm_kernel<128, 64, 16, 8, 4><<<dim3(HH / 64, BB / 128), 256>>>(
            pbel, RR, RR, nullptr, 0, RR,
            W_p1, HH, b_p1, nullptr, 0, ph1, 1);
        // p = h1 @ W_p2 + b_p2                             [B,128]
        gemm_kernel<64, 64, 16, 4, 4><<<dim3(2 * SS / 32 / 2, BB / 64), 256>>>(
            ph1, HH, HH, nullptr, 0, HH,
            W_p2, 2 * SS, b_p2, nullptr, 0, pp, 0);
        dist_kernel<<<(BB * SS) / 256, 256>>>(pp, noise_p, o_pmean, o_pstd, o_prior, nullptr, t);
        // posterior head: h2 = elu(bel @ W_q1[:R,:] + qpre_t)
        gemm_kernel<128, 64, 16, 8, 4><<<dim3(HH / 64, BB / 128), 256>>>(
            pbel, RR, RR, nullptr, 0, RR,
            W_q1, HH, nullptr, pqpre + (size_t)t * HH, TT * HH, ph2, 1);
        // q = h2 @ W_q2 + b_q2                             [B,128]
        gemm_kernel<64, 64, 16, 4, 4><<<dim3(2 * SS / 32 / 2, BB / 64), 256>>>(
            ph2, HH, HH, nullptr, 0, HH,
            W_q2, 2 * SS, b_q2, nullptr, 0, pq, 0);
        dist_kernel<<<(BB * SS) / 256, 256>>>(pq, noise_q, o_qmean, o_qstd, o_post, ppost, t);
    }
}

// round 3
// speedup vs baseline: 1.2555x; 1.2555x over previous
#include <cuda_runtime.h>
#include <cuda_bf16.h>
#include <math.h>
#include <stdint.h>

// Problem constants
constexpr int BB = 2048;   // batch
constexpr int TT = 64;     // time steps
constexpr int SS = 64;     // state dim
constexpr int AA = 16;     // action dim
constexpr int HH = 512;    // hidden
constexpr int RR = 512;    // belief dim
constexpr int EE = 1024;   // obs embedding dim

// ---------------- device scratch (no allocations allowed) ----------------
__device__ float g_x   [BB * HH];
__device__ float g_gi  [BB * 3 * RR];
__device__ float g_gh  [BB * 3 * RR];
__device__ float g_bel [BB * RR];
__device__ float g_post[BB * SS];
__device__ float g_h2  [BB * HH];
__device__ float g_q   [BB * 2 * SS];
__device__ float g_qpre[(size_t)BB * TT * HH];      // qpre during loop; h1 after loop
__device__ float g_pall[(size_t)BB * TT * 2 * SS];  // batched prior head output

// Pre-split weights: [N rows x K3pad cols] bf16, segments [Wh | Wh | Wl], zero pad
__device__ __nv_bfloat16 w_as [512 * 256];    // K=80  -> K3pad=256
__device__ __nv_bfloat16 w_ih [1536 * 1536];  // K=512 -> 1536
__device__ __nv_bfloat16 w_hh [1536 * 1536];
__device__ __nv_bfloat16 w_p1 [512 * 1536];
__device__ __nv_bfloat16 w_p2 [128 * 1536];
__device__ __nv_bfloat16 w_q1r[512 * 1536];
__device__ __nv_bfloat16 w_q1o[512 * 3072];   // K=1024 -> 3072
__device__ __nv_bfloat16 w_q2 [128 * 1536];

// ---------------- helpers ----------------
__device__ __forceinline__ uint32_t smem_u32(const void* p) {
    uint32_t a;
    asm("{ .reg .u64 t; cvta.to.shared.u64 t, %1; cvt.u32.u64 %0, t; }" : "=r"(a) : "l"(p));
    return a;
}

__device__ __forceinline__ void ldmatrix_x4(uint32_t* r, uint32_t addr) {
    asm volatile("ldmatrix.sync.aligned.m8n8.x4.shared.b16 {%0,%1,%2,%3}, [%4];"
                 : "=r"(r[0]), "=r"(r[1]), "=r"(r[2]), "=r"(r[3]) : "r"(addr));
}

__device__ __forceinline__ void mma_16816(float* d, const uint32_t* a,
                                          uint32_t b0, uint32_t b1) {
    asm volatile(
        "mma.sync.aligned.m16n8k16.row.col.f32.bf16.bf16.f32 "
        "{%0,%1,%2,%3}, {%4,%5,%6,%7}, {%8,%9}, {%0,%1,%2,%3};"
        : "+f"(d[0]), "+f"(d[1]), "+f"(d[2]), "+f"(d[3])
        : "r"(a[0]), "r"(a[1]), "r"(a[2]), "r"(a[3]), "r"(b0), "r"(b1));
}

// load + 3-term-split-convert one 8-elem A chunk (returns packed bf16x8)
__device__ __forceinline__ uint4 load_a_chunk(
    const float* __restrict__ A1, int lda1, int K1,
    const float* __restrict__ A2, int lda2,
    int Kseg, int K3, int m0, int idx, int k0)
{
    int row = idx >> 3, c = idx & 7;
    int k3 = k0 + c * 8;
    uint4 v; v.x = v.y = v.z = v.w = 0u;
    if (k3 < K3) {
        int seg = (k3 >= Kseg) + (k3 >= 2 * Kseg);
        int kk = k3 - seg * Kseg;
        const float* src = (kk < K1)
            ? A1 + (size_t)(m0 + row) * lda1 + kk
            : A2 + (size_t)(m0 + row) * lda2 + (kk - K1);
        float4 f0 = *reinterpret_cast<const float4*>(src);
        float4 f1 = *reinterpret_cast<const float4*>(src + 4);
        float f[8] = {f0.x, f0.y, f0.z, f0.w, f1.x, f1.y, f1.z, f1.w};
        uint16_t hb[8];
        if (seg == 1) {
#pragma unroll
            for (int j = 0; j < 8; ++j) {
                __nv_bfloat16 hi = __float2bfloat16(f[j]);
                hb[j] = __bfloat16_as_ushort(__float2bfloat16(f[j] - __bfloat162float(hi)));
            }
        } else {
#pragma unroll
            for (int j = 0; j < 8; ++j)
                hb[j] = __bfloat16_as_ushort(__float2bfloat16(f[j]));
        }
        v.x = (uint32_t)hb[0] | ((uint32_t)hb[1] << 16);
        v.y = (uint32_t)hb[2] | ((uint32_t)hb[3] << 16);
        v.z = (uint32_t)hb[4] | ((uint32_t)hb[5] << 16);
        v.w = (uint32_t)hb[6] | ((uint32_t)hb[7] << 16);
    }
    return v;
}

// ---------------- tensor-core GEMM (mma.sync, bf16 3-term split) ----------------
// C[M,N] = act( A[M,Kseg] @ Bmath[Kseg,N] + bias + addm )
// A fp32 (col-concat A1|A2), split on the fly; Bw bf16 [N x ldb], ldb = KT*64.
// CTA tile 128x64, K-tile 64, double-buffered smem + register prefetch.
// blockIdx.z==1 selects the alternate problem set (gi/gh fusion).
__global__ __launch_bounds__(256)
void tgemm(const float* __restrict__ A1, int lda1, int K1,
           const float* __restrict__ A2, int lda2,
           int Kseg, int KT,
           const __nv_bfloat16* __restrict__ Bw, int ldb,
           const float* __restrict__ bias,
           const float* __restrict__ addm, int ldadd,
           float* __restrict__ C, int ldc, int act,
           const float* __restrict__ A1b, const __nv_bfloat16* __restrict__ Bwb,
           const float* __restrict__ biasb, float* __restrict__ Cb)
{
    if (blockIdx.z == 1) { A1 = A1b; A2 = A1b; Bw = Bwb; bias = biasb; C = Cb; }

    __shared__ __align__(1024) unsigned char sm[49152];   // A: 2x16KB, B: 2x8KB
    const uint32_t smA = smem_u32(sm);
    const uint32_t smB = smA + 32768;

    const int tid = threadIdx.x;
    const int lane = tid & 31;
    const int wid = tid >> 5;
    const int wm = wid >> 1;            // 0..3
    const int wn = wid & 1;             // 0..1
    const int m0 = blockIdx.y * 128;
    const int n0 = blockIdx.x * 64;
    const int K3 = 3 * Kseg;

    float acc[2][4][4];
#pragma unroll
    for (int i = 0; i < 2; i++)
#pragma unroll
        for (int j = 0; j < 4; j++)
#pragma unroll
            for (int q = 0; q < 4; q++) acc[i][j][q] = 0.f;

    uint4 pa[4], pb[2];

    // prologue: tile 0 -> regs -> smem buf 0
#pragma unroll
    for (int it = 0; it < 4; ++it)
        pa[it] = load_a_chunk(A1, lda1, K1, A2, lda2, Kseg, K3, m0, tid + it * 256, 0);
#pragma unroll
    for (int it = 0; it < 2; ++it) {
        int idx = tid + it * 256;
        pb[it] = *reinterpret_cast<const uint4*>(
            Bw + (size_t)(n0 + (idx >> 3)) * ldb + (idx & 7) * 8);
    }
#pragma unroll
    for (int it = 0; it < 4; ++it) {
        int idx = tid + it * 256, row = idx >> 3, c = idx & 7;
        *reinterpret_cast<uint4*>(sm + row * 128 + (c ^ (row & 7)) * 16) = pa[it];
    }
#pragma unroll
    for (int it = 0; it < 2; ++it) {
        int idx = tid + it * 256, row = idx >> 3, c = idx & 7;
        *reinterpret_cast<uint4*>(sm + 32768 + row * 128 + (c ^ (row & 7)) * 16) = pb[it];
    }
    __syncthreads();

    for (int kt = 0; kt < KT; ++kt) {
        const int buf = kt & 1;
        const bool more = (kt + 1 < KT);
        // prefetch next tile into regs (LDGs issue before MMA phase)
        if (more) {
            const int k0 = (kt + 1) * 64;
#pragma unroll
            for (int it = 0; it < 4; ++it)
                pa[it] = load_a_chunk(A1, lda1, K1, A2, lda2, Kseg, K3, m0,
                                      tid + it * 256, k0);
#pragma unroll
            for (int it = 0; it < 2; ++it) {
                int idx = tid + it * 256;
                pb[it] = *reinterpret_cast<const uint4*>(
                    Bw + (size_t)(n0 + (idx >> 3)) * ldb + k0 + (idx & 7) * 8);
            }
        }

        // MMA over current buffer
        const uint32_t baseA = smA + buf * 16384;
        const uint32_t baseB = smB + buf * 8192;
#pragma unroll
        for (int ks = 0; ks < 4; ++ks) {
            uint32_t a[2][4], bq[2][4];
#pragma unroll
            for (int mt = 0; mt < 2; ++mt) {
                int row = wm * 32 + mt * 16 + (lane & 15);
                int kc = ks * 2 + (lane >> 4);
                ldmatrix_x4(a[mt], baseA + row * 128 + ((kc ^ (row & 7)) * 16));
            }
#pragma unroll
            for (int nb = 0; nb < 2; ++nb) {
                int row = wn * 32 + nb * 16 + (lane & 15);
                int kc = ks * 2 + (lane >> 4);
                ldmatrix_x4(bq[nb], baseB + row * 128 + ((kc ^ (row & 7)) * 16));
            }
#pragma unroll
            for (int mt = 0; mt < 2; ++mt) {
                mma_16816(acc[mt][0], a[mt], bq[0][0], bq[0][2]);
                mma_16816(acc[mt][1], a[mt], bq[0][1], bq[0][3]);
                mma_16816(acc[mt][2], a[mt], bq[1][0], bq[1][2]);
                mma_16816(acc[mt][3], a[mt], bq[1][1], bq[1][3]);
            }
        }

        // stage next tile into the other buffer
        if (more) {
            unsigned char* dstA = sm + (1 - buf) * 16384;
            unsigned char* dstB = sm + 32768 + (1 - buf) * 8192;
#pragma unroll
            for (int it = 0; it < 4; ++it) {
                int idx = tid + it * 256, row = idx >> 3, c = idx & 7;
                *reinterpret_cast<uint4*>(dstA + row * 128 + (c ^ (row & 7)) * 16) = pa[it];
            }
#pragma unroll
            for (int it = 0; it < 2; ++it) {
                int idx = tid + it * 256, row = idx >> 3, c = idx & 7;
                *reinterpret_cast<uint4*>(dstB + row * 128 + (c ^ (row & 7)) * 16) = pb[it];
            }
        }
        __syncthreads();
    }

    // ---- epilogue: fragments -> gmem with fused bias/add/ELU ----
    const int mbase = m0 + wm * 32;
    const int nbase = n0 + wn * 32;
#pragma unroll
    for (int mt = 0; mt < 2; ++mt) {
#pragma unroll
        for (int nt = 0; nt < 4; ++nt) {
            int col = nbase + nt * 8 + 2 * (lane & 3);
            float bx = 0.f, by = 0.f;
            if (bias) { bx = bias[col]; by = bias[col + 1]; }
#pragma unroll
            for (int h = 0; h < 2; ++h) {
                int row = mbase + mt * 16 + (lane >> 2) + h * 8;
                float vx = acc[mt][nt][2 * h + 0] + bx;
                float vy = acc[mt][nt][2 * h + 1] + by;
                if (addm) {
                    const float* ap = addm + (size_t)row * ldadd + col;
                    vx += ap[0]; vy += ap[1];
                }
                if (act == 1) {
                    vx = vx > 0.f ? vx : expm1f(vx);
                    vy = vy > 0.f ? vy : expm1f(vy);
                }
                *reinterpret_cast<float2*>(&C[(size_t)row * ldc + col]) =
                    make_float2(vx, vy);
            }
        }
    }
}

// ---------------- weight prep: fp32 -> [N x K3pad] bf16 [Wh|Wh|Wl] ----------------
__global__ void prep_w(const float* __restrict__ src, int K, int N, int K3pad,
                       int transpose, __nv_bfloat16* __restrict__ dst)
{
    int idx = blockIdx.x * blockDim.x + threadIdx.x;
    if (idx >= N * K3pad) return;
    int n = idx / K3pad, k3 = idx % K3pad;
    __nv_bfloat16 out;
    if (k3 >= 3 * K) out = __float2bfloat16(0.f);
    else {
        int seg = k3 / K, kk = k3 % K;
        float v = transpose ? src[(size_t)kk * N + n] : src[(size_t)n * K + kk];
        __nv_bfloat16 hi = __float2bfloat16(v);
        out = (seg < 2) ? hi : __float2bfloat16(v - __bfloat162float(hi));
    }
    dst[idx] = out;
}

// ---------------- elementwise ----------------
__global__ void copy_kernel(float* __restrict__ dst, const float* __restrict__ src, int n)
{
    int i = blockIdx.x * blockDim.x + threadIdx.x;
    if (i < n) dst[i] = src[i];
}

__device__ __forceinline__ float sigmoidf_(float x) { return 1.f / (1.f + expf(-x)); }

__global__ void gru_kernel(float* __restrict__ out_bel, int t)
{
    int idx = blockIdx.x * blockDim.x + threadIdx.x;
    if (idx >= BB * RR) return;
    int b = idx >> 9, r = idx & 511;
    const float* gi = g_gi + (size_t)b * (3 * RR);
    const float* gh = g_gh + (size_t)b * (3 * RR);
    float ir = gi[r], iz = gi[RR + r], in = gi[2 * RR + r];
    float hr = gh[r], hz = gh[RR + r], hn = gh[2 * RR + r];
    float bo = g_bel[idx];
    float rg = sigmoidf_(ir + hr);
    float zg = sigmoidf_(iz + hz);
    float nn = tanhf(in + rg * hn);
    float bn = (1.f - zg) * nn + zg * bo;
    g_bel[idx] = bn;
    out_bel[((size_t)b * TT + t) * RR + r] = bn;
}

__global__ void dist_q_kernel(const float* __restrict__ noise,
                              float* __restrict__ o_mean, float* __restrict__ o_std,
                              float* __restrict__ o_state, int t)
{
    int idx = blockIdx.x * blockDim.x + threadIdx.x;
    if (idx >= BB * SS) return;
    int b = idx >> 6, s = idx & 63;
    float m   = g_q[(size_t)b * (2 * SS) + s];
    float raw = g_q[(size_t)b * (2 * SS) + SS + s];
    float sp = raw > 20.f ? raw : log1pf(expf(raw));
    float sd = sp + 0.1f;
    float eps = noise[((size_t)b * TT + t) * SS + s];
    float st = m + sd * eps;
    size_t o = ((size_t)b * TT + t) * SS + s;
    o_mean[o] = m; o_std[o] = sd; o_state[o] = st;
    g_post[idx] = st;
}

__global__ void dist_p_kernel(const float* __restrict__ noise,
                              float* __restrict__ o_mean, float* __restrict__ o_std,
                              float* __restrict__ o_state)
{
    int idx = blockIdx.x * blockDim.x + threadIdx.x;
    if (idx >= BB * TT * SS) return;
    int s = idx & 63;
    int bt = idx >> 6;
    float m   = g_pall[(size_t)bt * (2 * SS) + s];
    float raw = g_pall[(size_t)bt * (2 * SS) + SS + s];
    float sp = raw > 20.f ? raw : log1pf(expf(raw));
    float sd = sp + 0.1f;
    float st = m + sd * noise[idx];
    o_mean[idx] = m; o_std[idx] = sd; o_state[idx] = st;
}

// ---------------- launch ----------------
extern "C" void kernel_launch(void* const* d_in, const int* in_sizes, int n_in,
                              void* d_out, int out_size)
{
    const float* posterior = (const float*)d_in[0];
    const float* belief    = (const float*)d_in[1];
    const float* actions   = (const float*)d_in[2];
    const float* obs       = (const float*)d_in[3];
    const float* noise_p   = (const float*)d_in[4];
    const float* noise_q   = (const float*)d_in[5];
    const float* W_as = (const float*)d_in[6];
    const float* b_as = (const float*)d_in[7];
    const float* W_ih = (const float*)d_in[8];
    const float* b_ih = (const float*)d_in[9];
    const float* W_hh = (const float*)d_in[10];
    const float* b_hh = (const float*)d_in[11];
    const float* W_p1 = (const float*)d_in[12];
    const float* b_p1 = (const float*)d_in[13];
    const float* W_p2 = (const float*)d_in[14];
    const float* b_p2 = (const float*)d_in[15];
    const float* W_q1 = (const float*)d_in[16];
    const float* b_q1 = (const float*)d_in[17];
    const float* W_q2 = (const float*)d_in[18];
    const float* b_q2 = (const float*)d_in[19];

    float *px, *pgi, *pgh, *pbel, *ppost, *ph2, *pq, *pqpre, *ppall;
    __nv_bfloat16 *pw_as, *pw_ih, *pw_hh, *pw_p1, *pw_p2, *pw_q1r, *pw_q1o, *pw_q2;
    cudaGetSymbolAddress((void**)&px,    g_x);
    cudaGetSymbolAddress((void**)&pgi,   g_gi);
    cudaGetSymbolAddress((void**)&pgh,   g_gh);
    cudaGetSymbolAddress((void**)&pbel,  g_bel);
    cudaGetSymbolAddress((void**)&ppost, g_post);
    cudaGetSymbolAddress((void**)&ph2,   g_h2);
    cudaGetSymbolAddress((void**)&pq,    g_q);
    cudaGetSymbolAddress((void**)&pqpre, g_qpre);
    cudaGetSymbolAddress((void**)&ppall, g_pall);
    cudaGetSymbolAddress((void**)&pw_as,  w_as);
    cudaGetSymbolAddress((void**)&pw_ih,  w_ih);
    cudaGetSymbolAddress((void**)&pw_hh,  w_hh);
    cudaGetSymbolAddress((void**)&pw_p1,  w_p1);
    cudaGetSymbolAddress((void**)&pw_p2,  w_p2);
    cudaGetSymbolAddress((void**)&pw_q1r, w_q1r);
    cudaGetSymbolAddress((void**)&pw_q1o, w_q1o);
    cudaGetSymbolAddress((void**)&pw_q2,  w_q2);

    float* out = (float*)d_out;
    const size_t BT = (size_t)BB * TT;
    float* o_pmean = out;
    float* o_pstd  = out + BT * SS;
    float* o_prior = out + 2 * BT * SS;
    float* o_bel   = out + 3 * BT * SS;
    float* o_qmean = out + 3 * BT * SS + BT * RR;
    float* o_qstd  = o_qmean + BT * SS;
    float* o_post  = o_qstd  + BT * SS;

    // init recurrent state
    copy_kernel<<<(BB * RR + 255) / 256, 256>>>(pbel, belief, BB * RR);
    copy_kernel<<<(BB * SS + 255) / 256, 256>>>(ppost, posterior, BB * SS);

    // weight prep (split + transpose-to-[NxK3pad])
    auto prep = [](const float* src, int K, int N, int K3pad, int tr, __nv_bfloat16* dst) {
        int n = N * K3pad;
        prep_w<<<(n + 255) / 256, 256>>>(src, K, N, K3pad, tr, dst);
    };
    prep(W_as,              80,  512,  256, 1, pw_as);
    prep(W_ih,             512, 1536, 1536, 0, pw_ih);
    prep(W_hh,             512, 1536, 1536, 0, pw_hh);
    prep(W_p1,             512,  512, 1536, 1, pw_p1);
    prep(W_p2,             512,  128, 1536, 1, pw_p2);
    prep(W_q1,             512,  512, 1536, 1, pw_q1r);
    prep(W_q1 + 512 * 512, 1024, 512, 3072, 1, pw_q1o);
    prep(W_q2,             512,  128, 1536, 1, pw_q2);

    // qpre[b,t,:] = obs[b,t,:] @ W_q1[R:, :] + b_q1   (batched over B*T)
    tgemm<<<dim3(8, (BB * TT) / 128, 1), 256>>>(
        obs, EE, EE, obs, EE, 1024, 48, pw_q1o, 3072,
        b_q1, nullptr, 0, pqpre, HH, 0,
        nullptr, nullptr, nullptr, nullptr);

    for (int t = 0; t < TT; ++t) {
        // x = elu(cat(post, a_t) @ W_as + b_as)
        tgemm<<<dim3(8, 16, 1), 256>>>(
            ppost, SS, SS, actions + (size_t)t * AA, TT * AA, 80, 4, pw_as, 256,
            b_as, nullptr, 0, px, HH, 1,
            nullptr, nullptr, nullptr, nullptr);
        // gi = x @ W_ih^T + b_ih  (z=0)   |   gh = bel @ W_hh^T + b_hh  (z=1)
        tgemm<<<dim3(24, 16, 2), 256>>>(
            px, HH, HH, px, HH, 512, 24, pw_ih, 1536,
            b_ih, nullptr, 0, pgi, 3 * RR, 0,
            pbel, pw_hh, b_hh, pgh);
        gru_kernel<<<(BB * RR) / 256, 256>>>(o_bel, t);
        // h2 = elu(bel @ W_q1[:R,:] + qpre_t)
        tgemm<<<dim3(8, 16, 1), 256>>>(
            pbel, RR, RR, pbel, RR, 512, 24, pw_q1r, 1536,
            nullptr, pqpre + (size_t)t * HH, TT * HH, ph2, HH, 1,
            nullptr, nullptr, nullptr, nullptr);
        // q = h2 @ W_q2 + b_q2
        tgemm<<<dim3(2, 16, 1), 256>>>(
            ph2, HH, HH, ph2, HH, 512, 24, pw_q2, 1536,
            b_q2, nullptr, 0, pq, 2 * SS, 0,
            nullptr, nullptr, nullptr, nullptr);
        dist_q_kernel<<<(BB * SS) / 256, 256>>>(noise_q, o_qmean, o_qstd, o_post, t);
    }

    // deferred prior head, batched over B*T (reuse g_qpre as h1)
    tgemm<<<dim3(8, (BB * TT) / 128, 1), 256>>>(
        o_bel, RR, RR, o_bel, RR, 512, 24, pw_p1, 1536,
        b_p1, nullptr, 0, pqpre, HH, 1,
        nullptr, nullptr, nullptr, nullptr);
    tgemm<<<dim3(2, (BB * TT) / 128, 1), 256>>>(
        pqpre, HH, HH, pqpre, HH, 512, 24, pw_p2, 1536,
        b_p2, nullptr, 0, ppall, 2 * SS, 0,
        nullptr, nullptr, nullptr, nullptr);
    dist_p_kernel<<<(BB * TT * SS + 255) / 256, 256>>>(noise_p, o_pmean, o_pstd, o_prior);
}

// round 4
// speedup vs baseline: 2.4735x; 1.9701x over previous
#include <cuda_runtime.h>
#include <cuda_bf16.h>
#include <math.h>
#include <stdint.h>

constexpr int BB = 2048, TT = 64, SS = 64, AA = 16, HH = 512, RR = 512, EE = 1024;

// ---------------- device scratch ----------------
__device__ float g_gi  [BB * 3 * RR];
__device__ float g_gh  [BB * 3 * RR];
__device__ float g_bel [BB * RR];
__device__ float g_post[BB * SS];
__device__ float g_q   [BB * 2 * SS];
__device__ float g_qpre[(size_t)BB * TT * HH];
__device__ float g_pall[(size_t)BB * TT * 2 * SS];

// split bf16 activation buffers: [M x 2K] = [hi | lo]
__device__ __nv_bfloat16 g_obs_split[(size_t)BB * TT * 2 * EE];  // 512MB; reused as h1_split
__device__ __nv_bfloat16 g_bel_all  [(size_t)BB * TT * 2 * RR];  // 256MB (for prior head)
__device__ __nv_bfloat16 g_x_split  [BB * 2 * HH];
__device__ __nv_bfloat16 g_bel_split[BB * 2 * RR];
__device__ __nv_bfloat16 g_h2_split [BB * 2 * HH];

// Pre-split weights: [N x K3pad] bf16, segments [Wh | Wh | Wl]
__device__ __nv_bfloat16 w_as [512 * 256];
__device__ __nv_bfloat16 w_ih [1536 * 1536];
__device__ __nv_bfloat16 w_hh [1536 * 1536];
__device__ __nv_bfloat16 w_p1 [512 * 1536];
__device__ __nv_bfloat16 w_p2 [128 * 1536];
__device__ __nv_bfloat16 w_q1r[512 * 1536];
__device__ __nv_bfloat16 w_q1o[512 * 3072];
__device__ __nv_bfloat16 w_q2 [128 * 1536];

// ---------------- helpers ----------------
__device__ __forceinline__ uint32_t smem_u32(const void* p) {
    uint32_t a;
    asm("{ .reg .u64 t; cvta.to.shared.u64 t, %1; cvt.u32.u64 %0, t; }" : "=r"(a) : "l"(p));
    return a;
}
__device__ __forceinline__ void ldmatrix_x4(uint32_t* r, uint32_t addr) {
    asm volatile("ldmatrix.sync.aligned.m8n8.x4.shared.b16 {%0,%1,%2,%3}, [%4];"
                 : "=r"(r[0]), "=r"(r[1]), "=r"(r[2]), "=r"(r[3]) : "r"(addr));
}
__device__ __forceinline__ void mma_16816(float* d, const uint32_t* a,
                                          uint32_t b0, uint32_t b1) {
    asm volatile(
        "mma.sync.aligned.m16n8k16.row.col.f32.bf16.bf16.f32 "
        "{%0,%1,%2,%3}, {%4,%5,%6,%7}, {%8,%9}, {%0,%1,%2,%3};"
        : "+f"(d[0]), "+f"(d[1]), "+f"(d[2]), "+f"(d[3])
        : "r"(a[0]), "r"(a[1]), "r"(a[2]), "r"(a[3]), "r"(b0), "r"(b1));
}
__device__ __forceinline__ void cp16(uint32_t s, const void* g) {
    asm volatile("cp.async.cg.shared.global [%0], [%1], 16;" :: "r"(s), "l"(g));
}
#define CP_COMMIT() asm volatile("cp.async.commit_group;" ::: "memory")

__device__ __forceinline__ void split2(float v, __nv_bfloat16& hi, __nv_bfloat16& lo) {
    hi = __float2bfloat16(v);
    lo = __float2bfloat16(v - __bfloat162float(hi));
}

// ---------- epilogue fragment writer (shared by both GEMMs) ----------
struct EpiArgs {
    const float* bias; const float* addm; int ldadd;
    float* C; int ldc;
    __nv_bfloat16* Cs; int Ntot;   // split output [M x 2*Ntot]
    int act;
};
__device__ __forceinline__ void epilogue(float acc[2][4][4], int m0, int n0,
                                         int wm, int wn, int lane, const EpiArgs& e) {
    const int mbase = m0 + wm * 32;
    const int nbase = n0 + wn * 32;
#pragma unroll
    for (int mt = 0; mt < 2; ++mt) {
#pragma unroll
        for (int nt = 0; nt < 4; ++nt) {
            int col = nbase + nt * 8 + 2 * (lane & 3);
            float bx = 0.f, by = 0.f;
            if (e.bias) { bx = e.bias[col]; by = e.bias[col + 1]; }
#pragma unroll
            for (int h = 0; h < 2; ++h) {
                int row = mbase + mt * 16 + (lane >> 2) + h * 8;
                float vx = acc[mt][nt][2 * h + 0] + bx;
                float vy = acc[mt][nt][2 * h + 1] + by;
                if (e.addm) {
                    const float* ap = e.addm + (size_t)row * e.ldadd + col;
                    vx += ap[0]; vy += ap[1];
                }
                if (e.act == 1) {
                    vx = vx > 0.f ? vx : expm1f(vx);
                    vy = vy > 0.f ? vy : expm1f(vy);
                }
                if (e.Cs) {
                    __nv_bfloat16 hx, lx, hy, ly;
                    split2(vx, hx, lx); split2(vy, hy, ly);
                    size_t base = (size_t)row * (2 * e.Ntot);
                    *reinterpret_cast<__nv_bfloat162*>(&e.Cs[base + col]) =
                        __nv_bfloat162(hx, hy);
                    *reinterpret_cast<__nv_bfloat162*>(&e.Cs[base + e.Ntot + col]) =
                        __nv_bfloat162(lx, ly);
                } else {
                    *reinterpret_cast<float2*>(&e.C[(size_t)row * e.ldc + col]) =
                        make_float2(vx, vy);
                }
            }
        }
    }
}

// ---------------- main GEMM: pre-split bf16 A, cp.async pipeline ----------------
// A: bf16 [M x lda] ([hi|lo], lda = 2*Kseg). Bw: bf16 [N x ldb] ([Wh|Wh|Wl]).
// CTA 128x64, K-tile 64, KT = 3*Kseg/64. blockIdx.z==1 -> alternate set.
__global__ __launch_bounds__(256)
void tgemm_bs(const __nv_bfloat16* __restrict__ A, int lda, int Kseg, int KT,
              const __nv_bfloat16* __restrict__ Bw, int ldb,
              const float* __restrict__ bias,
              const float* __restrict__ addm, int ldadd,
              float* __restrict__ C, int ldc,
              __nv_bfloat16* __restrict__ Cs, int Ntot, int act,
              const __nv_bfloat16* __restrict__ Aalt,
              const __nv_bfloat16* __restrict__ Bwalt,
              const float* __restrict__ biasalt, float* __restrict__ Calt)
{
    if (blockIdx.z == 1) { A = Aalt; Bw = Bwalt; bias = biasalt; C = Calt; }

    __shared__ __align__(1024) unsigned char sm[49152];   // A 2x16KB | B 2x8KB
    const uint32_t smA = smem_u32(sm);
    const uint32_t smB = smA + 32768;

    const int tid = threadIdx.x, lane = tid & 31, wid = tid >> 5;
    const int wm = wid >> 1, wn = wid & 1;
    const int m0 = blockIdx.y * 128, n0 = blockIdx.x * 64;
    const int K2 = 2 * Kseg;

    float acc[2][4][4];
#pragma unroll
    for (int i = 0; i < 2; i++)
#pragma unroll
        for (int j = 0; j < 4; j++)
#pragma unroll
            for (int q = 0; q < 4; q++) acc[i][j][q] = 0.f;

    auto stage = [&](int kt, int buf) {
        int k0 = kt * 64;
        int k0e = (k0 >= K2) ? k0 - K2 : k0;   // 3rd segment re-reads hi
        uint32_t dA = smA + buf * 16384, dB = smB + buf * 8192;
#pragma unroll
        for (int it = 0; it < 4; ++it) {
            int idx = tid + it * 256, row = idx >> 3, c = idx & 7;
            cp16(dA + row * 128 + ((c ^ (row & 7)) * 16),
                 A + (size_t)(m0 + row) * lda + k0e + c * 8);
        }
#pragma unroll
        for (int it = 0; it < 2; ++it) {
            int idx = tid + it * 256, row = idx >> 3, c = idx & 7;
            cp16(dB + row * 128 + ((c ^ (row & 7)) * 16),
                 Bw + (size_t)(n0 + row) * ldb + k0 + c * 8);
        }
        CP_COMMIT();
    };

    stage(0, 0);
    for (int kt = 0; kt < KT; ++kt) {
        const int buf = kt & 1;
        const bool more = (kt + 1 < KT);
        if (more) stage(kt + 1, 1 - buf);
        if (more) asm volatile("cp.async.wait_group 1;" ::: "memory");
        else      asm volatile("cp.async.wait_group 0;" ::: "memory");
        __syncthreads();

        const uint32_t baseA = smA + buf * 16384;
        const uint32_t baseB = smB + buf * 8192;
#pragma unroll
        for (int ks = 0; ks < 4; ++ks) {
            uint32_t a[2][4], bq[2][4];
#pragma unroll
            for (int mt = 0; mt < 2; ++mt) {
                int row = wm * 32 + mt * 16 + (lane & 15);
                int kc = ks * 2 + (lane >> 4);
                ldmatrix_x4(a[mt], baseA + row * 128 + ((kc ^ (row & 7)) * 16));
            }
#pragma unroll
            for (int nb = 0; nb < 2; ++nb) {
                int row = wn * 32 + nb * 16 + (lane & 15);
                int kc = ks * 2 + (lane >> 4);
                ldmatrix_x4(bq[nb], baseB + row * 128 + ((kc ^ (row & 7)) * 16));
            }
#pragma unroll
            for (int mt = 0; mt < 2; ++mt) {
                mma_16816(acc[mt][0], a[mt], bq[0][0], bq[0][2]);
                mma_16816(acc[mt][1], a[mt], bq[0][1], bq[0][3]);
                mma_16816(acc[mt][2], a[mt], bq[1][0], bq[1][2]);
                mma_16816(acc[mt][3], a[mt], bq[1][1], bq[1][3]);
            }
        }
        __syncthreads();
    }

    EpiArgs e{bias, addm, ldadd, C, ldc, Cs, Ntot, act};
    epilogue(acc, m0, n0, wm, wn, lane, e);
}

// ---------------- fp32-A GEMM (only for the small x GEMM, K=80) ----------------
__device__ __forceinline__ uint4 load_a_chunk(
    const float* __restrict__ A1, int lda1, int K1,
    const float* __restrict__ A2, int lda2,
    int Kseg, int K3, int m0, int idx, int k0)
{
    int row = idx >> 3, c = idx & 7;
    int k3 = k0 + c * 8;
    uint4 v; v.x = v.y = v.z = v.w = 0u;
    if (k3 < K3) {
        int seg = (k3 >= Kseg) + (k3 >= 2 * Kseg);
        int kk = k3 - seg * Kseg;
        const float* src = (kk < K1)
            ? A1 + (size_t)(m0 + row) * lda1 + kk
            : A2 + (size_t)(m0 + row) * lda2 + (kk - K1);
        float4 f0 = *reinterpret_cast<const float4*>(src);
        float4 f1 = *reinterpret_cast<const float4*>(src + 4);
        float f[8] = {f0.x, f0.y, f0.z, f0.w, f1.x, f1.y, f1.z, f1.w};
        uint16_t hb[8];
        if (seg == 1) {
#pragma unroll
            for (int j = 0; j < 8; ++j) {
                __nv_bfloat16 hi = __float2bfloat16(f[j]);
                hb[j] = __bfloat16_as_ushort(__float2bfloat16(f[j] - __bfloat162float(hi)));
            }
        } else {
#pragma unroll
            for (int j = 0; j < 8; ++j)
                hb[j] = __bfloat16_as_ushort(__float2bfloat16(f[j]));
        }
        v.x = (uint32_t)hb[0] | ((uint32_t)hb[1] << 16);
        v.y = (uint32_t)hb[2] | ((uint32_t)hb[3] << 16);
        v.z = (uint32_t)hb[4] | ((uint32_t)hb[5] << 16);
        v.w = (uint32_t)hb[6] | ((uint32_t)hb[7] << 16);
    }
    return v;
}

__global__ __launch_bounds__(256)
void tgemm_f32a(const float* __restrict__ A1, int lda1, int K1,
                const float* __restrict__ A2, int lda2,
                int Kseg, int KT,
                const __nv_bfloat16* __restrict__ Bw, int ldb,
                const float* __restrict__ bias,
                float* __restrict__ C, int ldc,
                __nv_bfloat16* __restrict__ Cs, int Ntot, int act)
{
    __shared__ __align__(1024) unsigned char sm[49152];
    const uint32_t smA = smem_u32(sm);
    const uint32_t smB = smA + 32768;
    const int tid = threadIdx.x, lane = tid & 31, wid = tid >> 5;
    const int wm = wid >> 1, wn = wid & 1;
    const int m0 = blockIdx.y * 128, n0 = blockIdx.x * 64;
    const int K3 = 3 * Kseg;

    float acc[2][4][4];
#pragma unroll
    for (int i = 0; i < 2; i++)
#pragma unroll
        for (int j = 0; j < 4; j++)
#pragma unroll
            for (int q = 0; q < 4; q++) acc[i][j][q] = 0.f;

    uint4 pa[4], pb[2];
#pragma unroll
    for (int it = 0; it < 4; ++it)
        pa[it] = load_a_chunk(A1, lda1, K1, A2, lda2, Kseg, K3, m0, tid + it * 256, 0);
#pragma unroll
    for (int it = 0; it < 2; ++it) {
        int idx = tid + it * 256;
        pb[it] = *reinterpret_cast<const uint4*>(
            Bw + (size_t)(n0 + (idx >> 3)) * ldb + (idx & 7) * 8);
    }
#pragma unroll
    for (int it = 0; it < 4; ++it) {
        int idx = tid + it * 256, row = idx >> 3, c = idx & 7;
        *reinterpret_cast<uint4*>(sm + row * 128 + (c ^ (row & 7)) * 16) = pa[it];
    }
#pragma unroll
    for (int it = 0; it < 2; ++it) {
        int idx = tid + it * 256, row = idx >> 3, c = idx & 7;
        *reinterpret_cast<uint4*>(sm + 32768 + row * 128 + (c ^ (row & 7)) * 16) = pb[it];
    }
    __syncthreads();

    for (int kt = 0; kt < KT; ++kt) {
        const int buf = kt & 1;
        const bool more = (kt + 1 < KT);
        if (more) {
            const int k0 = (kt + 1) * 64;
#pragma unroll
            for (int it = 0; it < 4; ++it)
                pa[it] = load_a_chunk(A1, lda1, K1, A2, lda2, Kseg, K3, m0,
                                      tid + it * 256, k0);
#pragma unroll
            for (int it = 0; it < 2; ++it) {
                int idx = tid + it * 256;
                pb[it] = *reinterpret_cast<const uint4*>(
                    Bw + (size_t)(n0 + (idx >> 3)) * ldb + k0 + (idx & 7) * 8);
            }
        }
        const uint32_t baseA = smA + buf * 16384;
        const uint32_t baseB = smB + buf * 8192;
#pragma unroll
        for (int ks = 0; ks < 4; ++ks) {
            uint32_t a[2][4], bq[2][4];
#pragma unroll
            for (int mt = 0; mt < 2; ++mt) {
                int row = wm * 32 + mt * 16 + (lane & 15);
                int kc = ks * 2 + (lane >> 4);
                ldmatrix_x4(a[mt], baseA + row * 128 + ((kc ^ (row & 7)) * 16));
            }
#pragma unroll
            for (int nb = 0; nb < 2; ++nb) {
                int row = wn * 32 + nb * 16 + (lane & 15);
                int kc = ks * 2 + (lane >> 4);
                ldmatrix_x4(bq[nb], baseB + row * 128 + ((kc ^ (row & 7)) * 16));
            }
#pragma unroll
            for (int mt = 0; mt < 2; ++mt) {
                mma_16816(acc[mt][0], a[mt], bq[0][0], bq[0][2]);
                mma_16816(acc[mt][1], a[mt], bq[0][1], bq[0][3]);
                mma_16816(acc[mt][2], a[mt], bq[1][0], bq[1][2]);
                mma_16816(acc[mt][3], a[mt], bq[1][1], bq[1][3]);
            }
        }
        if (more) {
            unsigned char* dstA = sm + (1 - buf) * 16384;
            unsigned char* dstB = sm + 32768 + (1 - buf) * 8192;
#pragma unroll
            for (int it = 0; it < 4; ++it) {
                int idx = tid + it * 256, row = idx >> 3, c = idx & 7;
                *reinterpret_cast<uint4*>(dstA + row * 128 + (c ^ (row & 7)) * 16) = pa[it];
            }
#pragma unroll
            for (int it = 0; it < 2; ++it) {
                int idx = tid + it * 256, row = idx >> 3, c = idx & 7;
                *reinterpret_cast<uint4*>(dstB + row * 128 + (c ^ (row & 7)) * 16) = pb[it];
            }
        }
        __syncthreads();
    }

    EpiArgs e{bias, nullptr, 0, C, ldc, Cs, Ntot, act};
    epilogue(acc, m0, n0, wm, wn, lane, e);
}

// ---------------- weight prep ----------------
__global__ void prep_w(const float* __restrict__ src, int K, int N, int K3pad,
                       int transpose, __nv_bfloat16* __restrict__ dst)
{
    int idx = blockIdx.x * blockDim.x + threadIdx.x;
    if (idx >= N * K3pad) return;
    int n = idx / K3pad, k3 = idx % K3pad;
    __nv_bfloat16 out;
    if (k3 >= 3 * K) out = __float2bfloat16(0.f);
    else {
        int seg = k3 / K, kk = k3 % K;
        float v = transpose ? src[(size_t)kk * N + n] : src[(size_t)n * K + kk];
        __nv_bfloat16 hi = __float2bfloat16(v);
        out = (seg < 2) ? hi : __float2bfloat16(v - __bfloat162float(hi));
    }
    dst[idx] = out;
}

// src [rows x K] fp32 -> dst [rows x 2K] bf16 [hi|lo]
__global__ void split_act(const float* __restrict__ src, __nv_bfloat16* __restrict__ dst,
                          long total, int K)
{
    long idx = (long)blockIdx.x * blockDim.x + threadIdx.x;
    if (idx >= total) return;
    long r = idx / K; int k = (int)(idx % K);
    __nv_bfloat16 hi, lo;
    split2(src[idx], hi, lo);
    dst[r * (2 * K) + k] = hi;
    dst[r * (2 * K) + K + k] = lo;
}

// ---------------- elementwise ----------------
__global__ void init_state(const float* __restrict__ bel0, const float* __restrict__ post0)
{
    int i = blockIdx.x * blockDim.x + threadIdx.x;
    if (i < BB * SS) g_post[i] = post0[i];
    if (i < BB * RR) {
        float v = bel0[i];
        g_bel[i] = v;
        int b = i >> 9, r = i & 511;
        __nv_bfloat16 hi, lo;
        split2(v, hi, lo);
        g_bel_split[b * 1024 + r] = hi;
        g_bel_split[b * 1024 + 512 + r] = lo;
    }
}

__device__ __forceinline__ float sigmoidf_(float x) { return 1.f / (1.f + expf(-x)); }

__global__ void gru_kernel(float* __restrict__ out_bel, int t)
{
    int idx = blockIdx.x * blockDim.x + threadIdx.x;
    if (idx >= BB * RR) return;
    int b = idx >> 9, r = idx & 511;
    const float* gi = g_gi + (size_t)b * (3 * RR);
    const float* gh = g_gh + (size_t)b * (3 * RR);
    float rg = sigmoidf_(gi[r] + gh[r]);
    float zg = sigmoidf_(gi[RR + r] + gh[RR + r]);
    float nn = tanhf(gi[2 * RR + r] + rg * gh[2 * RR + r]);
    float bn = (1.f - zg) * nn + zg * g_bel[idx];
    g_bel[idx] = bn;
    out_bel[((size_t)b * TT + t) * RR + r] = bn;
    __nv_bfloat16 hi, lo;
    split2(bn, hi, lo);
    g_bel_split[b * 1024 + r] = hi;
    g_bel_split[b * 1024 + 512 + r] = lo;
    size_t ra = ((size_t)b * TT + t) * 1024;
    g_bel_all[ra + r] = hi;
    g_bel_all[ra + 512 + r] = lo;
}

__global__ void dist_q_kernel(const float* __restrict__ noise,
                              float* __restrict__ o_mean, float* __restrict__ o_std,
                              float* __restrict__ o_state, int t)
{
    int idx = blockIdx.x * blockDim.x + threadIdx.x;
    if (idx >= BB * SS) return;
    int b = idx >> 6, s = idx & 63;
    float m   = g_q[(size_t)b * (2 * SS) + s];
    float raw = g_q[(size_t)b * (2 * SS) + SS + s];
    float sp = raw > 20.f ? raw : log1pf(expf(raw));
    float sd = sp + 0.1f;
    float eps = noise[((size_t)b * TT + t) * SS + s];
    float st = m + sd * eps;
    size_t o = ((size_t)b * TT + t) * SS + s;
    o_mean[o] = m; o_std[o] = sd; o_state[o] = st;
    g_post[idx] = st;
}

__global__ void dist_p_kernel(const float* __restrict__ noise,
                              float* __restrict__ o_mean, float* __restrict__ o_std,
                              float* __restrict__ o_state)
{
    int idx = blockIdx.x * blockDim.x + threadIdx.x;
    if (idx >= BB * TT * SS) return;
    int s = idx & 63;
    int bt = idx >> 6;
    float m   = g_pall[(size_t)bt * (2 * SS) + s];
    float raw = g_pall[(size_t)bt * (2 * SS) + SS + s];
    float sp = raw > 20.f ? raw : log1pf(expf(raw));
    float sd = sp + 0.1f;
    float st = m + sd * noise[idx];
    o_mean[idx] = m; o_std[idx] = sd; o_state[idx] = st;
}

// ---------------- launch ----------------
extern "C" void kernel_launch(void* const* d_in, const int* in_sizes, int n_in,
                              void* d_out, int out_size)
{
    const float* posterior = (const float*)d_in[0];
    const float* belief    = (const float*)d_in[1];
    const float* actions   = (const float*)d_in[2];
    const float* obs       = (const float*)d_in[3];
    const float* noise_p   = (const float*)d_in[4];
    const float* noise_q   = (const float*)d_in[5];
    const float* W_as = (const float*)d_in[6];
    const float* b_as = (const float*)d_in[7];
    const float* W_ih = (const float*)d_in[8];
    const float* b_ih = (const float*)d_in[9];
    const float* W_hh = (const float*)d_in[10];
    const float* b_hh = (const float*)d_in[11];
    const float* W_p1 = (const float*)d_in[12];
    const float* b_p1 = (const float*)d_in[13];
    const float* W_p2 = (const float*)d_in[14];
    const float* b_p2 = (const float*)d_in[15];
    const float* W_q1 = (const float*)d_in[16];
    const float* b_q1 = (const float*)d_in[17];
    const float* W_q2 = (const float*)d_in[18];
    const float* b_q2 = (const float*)d_in[19];

    float *pgi, *pgh, *pbel, *ppost, *pq, *pqpre, *ppall;
    __nv_bfloat16 *pobs, *pbela, *pxs, *pbels, *ph2s;
    __nv_bfloat16 *pw_as, *pw_ih, *pw_hh, *pw_p1, *pw_p2, *pw_q1r, *pw_q1o, *pw_q2;
    cudaGetSymbolAddress((void**)&pgi,   g_gi);
    cudaGetSymbolAddress((void**)&pgh,   g_gh);
    cudaGetSymbolAddress((void**)&pbel,  g_bel);
    cudaGetSymbolAddress((void**)&ppost, g_post);
    cudaGetSymbolAddress((void**)&pq,    g_q);
    cudaGetSymbolAddress((void**)&pqpre, g_qpre);
    cudaGetSymbolAddress((void**)&ppall, g_pall);
    cudaGetSymbolAddress((void**)&pobs,  g_obs_split);
    cudaGetSymbolAddress((void**)&pbela, g_bel_all);
    cudaGetSymbolAddress((void**)&pxs,   g_x_split);
    cudaGetSymbolAddress((void**)&pbels, g_bel_split);
    cudaGetSymbolAddress((void**)&ph2s,  g_h2_split);
    cudaGetSymbolAddress((void**)&pw_as,  w_as);
    cudaGetSymbolAddress((void**)&pw_ih,  w_ih);
    cudaGetSymbolAddress((void**)&pw_hh,  w_hh);
    cudaGetSymbolAddress((void**)&pw_p1,  w_p1);
    cudaGetSymbolAddress((void**)&pw_p2,  w_p2);
    cudaGetSymbolAddress((void**)&pw_q1r, w_q1r);
    cudaGetSymbolAddress((void**)&pw_q1o, w_q1o);
    cudaGetSymbolAddress((void**)&pw_q2,  w_q2);

    float* out = (float*)d_out;
    const size_t BT = (size_t)BB * TT;
    float* o_pmean = out;
    float* o_pstd  = out + BT * SS;
    float* o_prior = out + 2 * BT * SS;
    float* o_bel   = out + 3 * BT * SS;
    float* o_qmean = out + 3 * BT * SS + BT * RR;
    float* o_qstd  = o_qmean + BT * SS;
    float* o_post  = o_qstd  + BT * SS;

    init_state<<<(BB * RR + 255) / 256, 256>>>(belief, posterior);

    auto prep = [](const float* src, int K, int N, int K3pad, int tr, __nv_bfloat16* dst) {
        int n = N * K3pad;
        prep_w<<<(n + 255) / 256, 256>>>(src, K, N, K3pad, tr, dst);
    };
    prep(W_as,              80,  512,  256, 1, pw_as);
    prep(W_ih,             512, 1536, 1536, 0, pw_ih);
    prep(W_hh,             512, 1536, 1536, 0, pw_hh);
    prep(W_p1,             512,  512, 1536, 1, pw_p1);
    prep(W_p2,             512,  128, 1536, 1, pw_p2);
    prep(W_q1,             512,  512, 1536, 1, pw_q1r);
    prep(W_q1 + 512 * 512, 1024, 512, 3072, 1, pw_q1o);
    prep(W_q2,             512,  128, 1536, 1, pw_q2);

    // split obs -> [131072 x 2048] bf16, then qpre GEMM
    {
        long total = (long)BT * EE;
        split_act<<<(unsigned)((total + 255) / 256), 256>>>(obs, pobs, total, EE);
    }
    tgemm_bs<<<dim3(8, (unsigned)(BT / 128), 1), 256>>>(
        pobs, 2 * EE, EE, 48, pw_q1o, 3072,
        b_q1, nullptr, 0, pqpre, HH, nullptr, 0, 0,
        nullptr, nullptr, nullptr, nullptr);

    for (int t = 0; t < TT; ++t) {
        // x_split = split(elu(cat(post, a_t) @ W_as + b_as))
        tgemm_f32a<<<dim3(8, 16), 256>>>(
            ppost, SS, SS, actions + (size_t)t * AA, TT * AA, 80, 4, pw_as, 256,
            b_as, nullptr, 0, pxs, HH, 1);
        // gi (z=0) | gh (z=1)
        tgemm_bs<<<dim3(24, 16, 2), 256>>>(
            pxs, 2 * HH, HH, 24, pw_ih, 1536,
            b_ih, nullptr, 0, pgi, 3 * RR, nullptr, 0, 0,
            pbels, pw_hh, b_hh, pgh);
        gru_kernel<<<(BB * RR) / 256, 256>>>(o_bel, t);
        // h2_split = split(elu(bel @ W_q1[:R,:] + qpre_t))
        tgemm_bs<<<dim3(8, 16, 1), 256>>>(
            pbels, 2 * RR, RR, 24, pw_q1r, 1536,
            nullptr, pqpre + (size_t)t * HH, TT * HH, nullptr, 0, ph2s, HH, 1,
            nullptr, nullptr, nullptr, nullptr);
        // q = h2 @ W_q2 + b_q2
        tgemm_bs<<<dim3(2, 16, 1), 256>>>(
            ph2s, 2 * HH, HH, 24, pw_q2, 1536,
            b_q2, nullptr, 0, pq, 2 * SS, nullptr, 0, 0,
            nullptr, nullptr, nullptr, nullptr);
        dist_q_kernel<<<(BB * SS) / 256, 256>>>(noise_q, o_qmean, o_qstd, o_post, t);
    }

    // deferred prior head over all B*T (h1_split aliases g_obs_split)
    tgemm_bs<<<dim3(8, (unsigned)(BT / 128), 1), 256>>>(
        pbela, 2 * RR, RR, 24, pw_p1, 1536,
        b_p1, nullptr, 0, nullptr, 0, pobs, HH, 1,
        nullptr, nullptr, nullptr, nullptr);
    tgemm_bs<<<dim3(2, (unsigned)(BT / 128), 1), 256>>>(
        pobs, 2 * HH, HH, 24, pw_p2, 1536,
        b_p2, nullptr, 0, ppall, 2 * SS, nullptr, 0, 0,
        nullptr, nullptr, nullptr, nullptr);
    dist_p_kernel<<<((unsigned)(BT * SS) + 255) / 256, 256>>>(noise_p, o_pmean, o_pstd, o_prior);
}

// round 5
// speedup vs baseline: 2.5288x; 1.0224x over previous
#include <cuda_runtime.h>
#include <cuda_bf16.h>
#include <math.h>
#include <stdint.h>

constexpr int BB = 2048, TT = 64, SS = 64, AA = 16, HH = 512, RR = 512, EE = 1024;

// ---------------- device scratch ----------------
__device__ float g_gi  [BB * 3 * RR];
__device__ float g_gh  [BB * 3 * RR];
__device__ float g_bel [BB * RR];
__device__ float g_qpart[4 * BB * 128];
__device__ float g_qpre   [(size_t)BB * TT * HH];
__device__ float g_act_pre[(size_t)BB * TT * HH];
__device__ float g_pall   [(size_t)BB * TT * 2 * SS];

__device__ __nv_bfloat16 g_obs_split[(size_t)BB * TT * 2 * EE];  // reused as h1_split
__device__ __nv_bfloat16 g_bel_all  [(size_t)BB * TT * 2 * RR];
__device__ __nv_bfloat16 g_act_pad  [(size_t)BB * TT * 64];
__device__ __nv_bfloat16 g_x_split  [BB * 2 * HH];
__device__ __nv_bfloat16 g_bel_split[BB * 2 * RR];
__device__ __nv_bfloat16 g_h2_split [BB * 2 * HH];
__device__ __nv_bfloat16 g_post_split[BB * 128];

// Pre-split weights: [N x K3pad] bf16, segments [Wh | Wh | Wl]
__device__ __nv_bfloat16 w_as1[512 * 192];   // state part, K=64
__device__ __nv_bfloat16 w_as2[512 * 64];    // action part, K=16 (+pad)
__device__ __nv_bfloat16 w_ih [1536 * 1536];
__device__ __nv_bfloat16 w_hh [1536 * 1536];
__device__ __nv_bfloat16 w_p1 [512 * 1536];
__device__ __nv_bfloat16 w_p2 [128 * 1536];
__device__ __nv_bfloat16 w_q1r[512 * 1536];
__device__ __nv_bfloat16 w_q1o[512 * 3072];
__device__ __nv_bfloat16 w_q2 [128 * 1536];

// ---------------- helpers ----------------
__device__ __forceinline__ uint32_t smem_u32(const void* p) {
    uint32_t a;
    asm("{ .reg .u64 t; cvta.to.shared.u64 t, %1; cvt.u32.u64 %0, t; }" : "=r"(a) : "l"(p));
    return a;
}
__device__ __forceinline__ void ldmatrix_x4(uint32_t* r, uint32_t addr) {
    asm volatile("ldmatrix.sync.aligned.m8n8.x4.shared.b16 {%0,%1,%2,%3}, [%4];"
                 : "=r"(r[0]), "=r"(r[1]), "=r"(r[2]), "=r"(r[3]) : "r"(addr));
}
__device__ __forceinline__ void mma_16816(float* d, const uint32_t* a,
                                          uint32_t b0, uint32_t b1) {
    asm volatile(
        "mma.sync.aligned.m16n8k16.row.col.f32.bf16.bf16.f32 "
        "{%0,%1,%2,%3}, {%4,%5,%6,%7}, {%8,%9}, {%0,%1,%2,%3};"
        : "+f"(d[0]), "+f"(d[1]), "+f"(d[2]), "+f"(d[3])
        : "r"(a[0]), "r"(a[1]), "r"(a[2]), "r"(a[3]), "r"(b0), "r"(b1));
}
__device__ __forceinline__ void cp16(uint32_t s, const void* g) {
    asm volatile("cp.async.cg.shared.global [%0], [%1], 16;" :: "r"(s), "l"(g));
}
#define CP_COMMIT() asm volatile("cp.async.commit_group;" ::: "memory")

__device__ __forceinline__ void split2(float v, __nv_bfloat16& hi, __nv_bfloat16& lo) {
    hi = __float2bfloat16(v);
    lo = __float2bfloat16(v - __bfloat162float(hi));
}

// ---------------- GEMM problem descriptor ----------------
struct GProb {
    const __nv_bfloat16* A; int lda; int Kseg; int KT;
    const __nv_bfloat16* B; int ldb;
    const float* bias; const float* addm; int ldadd;
    float* C; int ldc;
    __nv_bfloat16* Cs; int Ntot;     // split bf16 output [M x 2*Ntot]
    int act;                         // 1 = ELU
    int ktz;                         // >0: k-tiles per z-slice (split-K)
    int cstride;                     // partial-C stride per z
};

// CTA 128x64, K-tile 64, 2-stage cp.async. blockIdx.x < nx0 -> p0 else p1.
__global__ __launch_bounds__(256)
void tgemm(GProb p0, GProb p1, int nx0)
{
    GProb p; int bx = blockIdx.x;
    if (bx < nx0) p = p0; else { p = p1; bx -= nx0; }

    __shared__ __align__(1024) unsigned char sm[49152];   // A 2x16KB | B 2x8KB
    const uint32_t smA = smem_u32(sm);
    const uint32_t smB = smA + 32768;

    const int tid = threadIdx.x, lane = tid & 31, wid = tid >> 5;
    const int wm = wid >> 1, wn = wid & 1;
    const int m0 = blockIdx.y * 128, n0 = bx * 64;
    const int K2 = 2 * p.Kseg;

    int ktb = 0, kte = p.KT;
    float* Cout = p.C;
    if (p.ktz > 0) {
        ktb = blockIdx.z * p.ktz; kte = ktb + p.ktz;
        Cout = p.C + (size_t)blockIdx.z * p.cstride;
    }

    float acc[2][4][4];
#pragma unroll
    for (int i = 0; i < 2; i++)
#pragma unroll
        for (int j = 0; j < 4; j++)
#pragma unroll
            for (int q = 0; q < 4; q++) acc[i][j][q] = 0.f;

    auto stage = [&](int kt, int buf) {
        int k0 = kt * 64;
        int k0e = (k0 >= K2) ? k0 - K2 : k0;   // 3rd segment re-reads hi
        uint32_t dA = smA + buf * 16384, dB = smB + buf * 8192;
#pragma unroll
        for (int it = 0; it < 4; ++it) {
            int idx = tid + it * 256, row = idx >> 3, c = idx & 7;
            cp16(dA + row * 128 + ((c ^ (row & 7)) * 16),
                 p.A + (size_t)(m0 + row) * p.lda + k0e + c * 8);
        }
#pragma unroll
        for (int it = 0; it < 2; ++it) {
            int idx = tid + it * 256, row = idx >> 3, c = idx & 7;
            cp16(dB + row * 128 + ((c ^ (row & 7)) * 16),
                 p.B + (size_t)(n0 + row) * p.ldb + kt * 64 + c * 8);
        }
        CP_COMMIT();
    };

    stage(ktb, 0);
    for (int kt = ktb; kt < kte; ++kt) {
        const int buf = (kt - ktb) & 1;
        const bool more = (kt + 1 < kte);
        if (more) stage(kt + 1, 1 - buf);
        if (more) asm volatile("cp.async.wait_group 1;" ::: "memory");
        else      asm volatile("cp.async.wait_group 0;" ::: "memory");
        __syncthreads();

        const uint32_t baseA = smA + buf * 16384;
        const uint32_t baseB = smB + buf * 8192;
#pragma unroll
        for (int ks = 0; ks < 4; ++ks) {
            uint32_t a[2][4], bq[2][4];
#pragma unroll
            for (int mt = 0; mt < 2; ++mt) {
                int row = wm * 32 + mt * 16 + (lane & 15);
                int kc = ks * 2 + (lane >> 4);
                ldmatrix_x4(a[mt], baseA + row * 128 + ((kc ^ (row & 7)) * 16));
            }
#pragma unroll
            for (int nb = 0; nb < 2; ++nb) {
                int row = wn * 32 + nb * 16 + (lane & 15);
                int kc = ks * 2 + (lane >> 4);
                ldmatrix_x4(bq[nb], baseB + row * 128 + ((kc ^ (row & 7)) * 16));
            }
#pragma unroll
            for (int mt = 0; mt < 2; ++mt) {
                mma_16816(acc[mt][0], a[mt], bq[0][0], bq[0][2]);
                mma_16816(acc[mt][1], a[mt], bq[0][1], bq[0][3]);
                mma_16816(acc[mt][2], a[mt], bq[1][0], bq[1][2]);
                mma_16816(acc[mt][3], a[mt], bq[1][1], bq[1][3]);
            }
        }
        __syncthreads();
    }

    // ---- epilogue ----
    const int mbase = m0 + wm * 32;
    const int nbase = n0 + wn * 32;
#pragma unroll
    for (int mt = 0; mt < 2; ++mt) {
#pragma unroll
        for (int nt = 0; nt < 4; ++nt) {
            int col = nbase + nt * 8 + 2 * (lane & 3);
            float bxv = 0.f, byv = 0.f;
            if (p.bias) { bxv = p.bias[col]; byv = p.bias[col + 1]; }
#pragma unroll
            for (int h = 0; h < 2; ++h) {
                int row = mbase + mt * 16 + (lane >> 2) + h * 8;
                float vx = acc[mt][nt][2 * h + 0] + bxv;
                float vy = acc[mt][nt][2 * h + 1] + byv;
                if (p.addm) {
                    const float* ap = p.addm + (size_t)row * p.ldadd + col;
                    vx += ap[0]; vy += ap[1];
                }
                if (p.act == 1) {
                    vx = vx > 0.f ? vx : expm1f(vx);
                    vy = vy > 0.f ? vy : expm1f(vy);
                }
                if (p.Cs) {
                    __nv_bfloat16 hx, lx, hy, ly;
                    split2(vx, hx, lx); split2(vy, hy, ly);
                    size_t base = (size_t)row * (2 * p.Ntot);
                    *reinterpret_cast<__nv_bfloat162*>(&p.Cs[base + col]) =
                        __nv_bfloat162(hx, hy);
                    *reinterpret_cast<__nv_bfloat162*>(&p.Cs[base + p.Ntot + col]) =
                        __nv_bfloat162(lx, ly);
                } else {
                    *reinterpret_cast<float2*>(&Cout[(size_t)row * p.ldc + col]) =
                        make_float2(vx, vy);
                }
            }
        }
    }
}

// ---------------- weight prep ----------------
__global__ void prep_w(const float* __restrict__ src, int K, int N, int K3pad,
                       int transpose, __nv_bfloat16* __restrict__ dst)
{
    int idx = blockIdx.x * blockDim.x + threadIdx.x;
    if (idx >= N * K3pad) return;
    int n = idx / K3pad, k3 = idx % K3pad;
    __nv_bfloat16 out;
    if (k3 >= 3 * K) out = __float2bfloat16(0.f);
    else {
        int seg = k3 / K, kk = k3 % K;
        float v = transpose ? src[(size_t)kk * N + n] : src[(size_t)n * K + kk];
        __nv_bfloat16 hi = __float2bfloat16(v);
        out = (seg < 2) ? hi : __float2bfloat16(v - __bfloat162float(hi));
    }
    dst[idx] = out;
}

// src [rows x K] fp32 -> dst [rows x 2K] bf16 [hi|lo]
__global__ void split_act(const float* __restrict__ src, __nv_bfloat16* __restrict__ dst,
                          long total, int K)
{
    long idx = (long)blockIdx.x * blockDim.x + threadIdx.x;
    if (idx >= total) return;
    long r = idx / K; int k = (int)(idx % K);
    __nv_bfloat16 hi, lo;
    split2(src[idx], hi, lo);
    dst[r * (2 * K) + k] = hi;
    dst[r * (2 * K) + K + k] = lo;
}

// actions [B*T x 16] -> [B*T x 64] = [hi|lo|hi|0]
__global__ void act_split_pad(const float* __restrict__ a)
{
    int idx = blockIdx.x * blockDim.x + threadIdx.x;
    if (idx >= BB * TT * AA) return;
    int bt = idx >> 4, k = idx & 15;
    __nv_bfloat16 hi, lo;
    split2(a[idx], hi, lo);
    __nv_bfloat16* d = g_act_pad + (size_t)bt * 64;
    d[k] = hi; d[16 + k] = lo; d[32 + k] = hi; d[48 + k] = __float2bfloat16(0.f);
}

// ---------------- elementwise ----------------
__global__ void init_state(const float* __restrict__ bel0, const float* __restrict__ post0)
{
    int i = blockIdx.x * blockDim.x + threadIdx.x;
    if (i < BB * SS) {
        int b = i >> 6, s = i & 63;
        __nv_bfloat16 hi, lo;
        split2(post0[i], hi, lo);
        g_post_split[b * 128 + s] = hi;
        g_post_split[b * 128 + 64 + s] = lo;
    }
    if (i < BB * RR) {
        float v = bel0[i];
        g_bel[i] = v;
        int b = i >> 9, r = i & 511;
        __nv_bfloat16 hi, lo;
        split2(v, hi, lo);
        g_bel_split[b * 1024 + r] = hi;
        g_bel_split[b * 1024 + 512 + r] = lo;
    }
}

__device__ __forceinline__ float sigmoidf_(float x) { return 1.f / (1.f + expf(-x)); }

__global__ void gru_kernel(float* __restrict__ out_bel, int t)
{
    int idx = blockIdx.x * blockDim.x + threadIdx.x;
    if (idx >= BB * RR) return;
    int b = idx >> 9, r = idx & 511;
    const float* gi = g_gi + (size_t)b * (3 * RR);
    const float* gh = g_gh + (size_t)b * (3 * RR);
    float rg = sigmoidf_(gi[r] + gh[r]);
    float zg = sigmoidf_(gi[RR + r] + gh[RR + r]);
    float nn = tanhf(gi[2 * RR + r] + rg * gh[2 * RR + r]);
    float bn = (1.f - zg) * nn + zg * g_bel[idx];
    g_bel[idx] = bn;
    out_bel[((size_t)b * TT + t) * RR + r] = bn;
    __nv_bfloat16 hi, lo;
    split2(bn, hi, lo);
    g_bel_split[b * 1024 + r] = hi;
    g_bel_split[b * 1024 + 512 + r] = lo;
    size_t ra = ((size_t)b * TT + t) * 1024;
    g_bel_all[ra + r] = hi;
    g_bel_all[ra + 512 + r] = lo;
}

// fused split-K reduce + distribution + post_split write
__global__ void dist_q_kernel(const float* __restrict__ noise,
                              const float* __restrict__ bq2,
                              float* __restrict__ o_mean, float* __restrict__ o_std,
                              float* __restrict__ o_state, int t)
{
    int idx = blockIdx.x * blockDim.x + threadIdx.x;
    if (idx >= BB * SS) return;
    int b = idx >> 6, s = idx & 63;
    float m = bq2[s], raw = bq2[SS + s];
#pragma unroll
    for (int z = 0; z < 4; ++z) {
        m   += g_qpart[z * BB * 128 + b * 128 + s];
        raw += g_qpart[z * BB * 128 + b * 128 + SS + s];
    }
    float sp = raw > 20.f ? raw : log1pf(expf(raw));
    float sd = sp + 0.1f;
    float eps = noise[((size_t)b * TT + t) * SS + s];
    float st = m + sd * eps;
    size_t o = ((size_t)b * TT + t) * SS + s;
    o_mean[o] = m; o_std[o] = sd; o_state[o] = st;
    __nv_bfloat16 hi, lo;
    split2(st, hi, lo);
    g_post_split[b * 128 + s] = hi;
    g_post_split[b * 128 + 64 + s] = lo;
}

__global__ void dist_p_kernel(const float* __restrict__ noise,
                              float* __restrict__ o_mean, float* __restrict__ o_std,
                              float* __restrict__ o_state)
{
    int idx = blockIdx.x * blockDim.x + threadIdx.x;
    if (idx >= BB * TT * SS) return;
    int s = idx & 63;
    int bt = idx >> 6;
    float m   = g_pall[(size_t)bt * (2 * SS) + s];
    float raw = g_pall[(size_t)bt * (2 * SS) + SS + s];
    float sp = raw > 20.f ? raw : log1pf(expf(raw));
    float sd = sp + 0.1f;
    float st = m + sd * noise[idx];
    o_mean[idx] = m; o_std[idx] = sd; o_state[idx] = st;
}

// ---------------- launch ----------------
static GProb mkprob(const __nv_bfloat16* A, int lda, int Kseg, int KT,
                    const __nv_bfloat16* B, int ldb,
                    const float* bias, const float* addm, int ldadd,
                    float* C, int ldc, __nv_bfloat16* Cs, int Ntot, int act,
                    int ktz = 0, int cstride = 0)
{
    GProb p{A, lda, Kseg, KT, B, ldb, bias, addm, ldadd, C, ldc, Cs, Ntot, act,
            ktz, cstride};
    return p;
}

extern "C" void kernel_launch(void* const* d_in, const int* in_sizes, int n_in,
                              void* d_out, int out_size)
{
    const float* posterior = (const float*)d_in[0];
    const float* belief    = (const float*)d_in[1];
    const float* actions   = (const float*)d_in[2];
    const float* obs       = (const float*)d_in[3];
    const float* noise_p   = (const float*)d_in[4];
    const float* noise_q   = (const float*)d_in[5];
    const float* W_as = (const float*)d_in[6];
    const float* b_as = (const float*)d_in[7];
    const float* W_ih = (const float*)d_in[8];
    const float* b_ih = (const float*)d_in[9];
    const float* W_hh = (const float*)d_in[10];
    const float* b_hh = (const float*)d_in[11];
    const float* W_p1 = (const float*)d_in[12];
    const float* b_p1 = (const float*)d_in[13];
    const float* W_p2 = (const float*)d_in[14];
    const float* b_p2 = (const float*)d_in[15];
    const float* W_q1 = (const float*)d_in[16];
    const float* b_q1 = (const float*)d_in[17];
    const float* W_q2 = (const float*)d_in[18];
    const float* b_q2 = (const float*)d_in[19];

    float *pgi, *pgh, *pqpre, *pactpre, *ppall, *pqpart;
    __nv_bfloat16 *pobs, *pbela, *pactpad, *pxs, *pbels, *ph2s, *pposts;
    __nv_bfloat16 *pw_as1, *pw_as2, *pw_ih, *pw_hh, *pw_p1, *pw_p2, *pw_q1r, *pw_q1o, *pw_q2;
    cudaGetSymbolAddress((void**)&pgi,     g_gi);
    cudaGetSymbolAddress((void**)&pgh,     g_gh);
    cudaGetSymbolAddress((void**)&pqpre,   g_qpre);
    cudaGetSymbolAddress((void**)&pactpre, g_act_pre);
    cudaGetSymbolAddress((void**)&ppall,   g_pall);
    cudaGetSymbolAddress((void**)&pqpart,  g_qpart);
    cudaGetSymbolAddress((void**)&pobs,    g_obs_split);
    cudaGetSymbolAddress((void**)&pbela,   g_bel_all);
    cudaGetSymbolAddress((void**)&pactpad, g_act_pad);
    cudaGetSymbolAddress((void**)&pxs,     g_x_split);
    cudaGetSymbolAddress((void**)&pbels,   g_bel_split);
    cudaGetSymbolAddress((void**)&ph2s,    g_h2_split);
    cudaGetSymbolAddress((void**)&pposts,  g_post_split);
    cudaGetSymbolAddress((void**)&pw_as1,  w_as1);
    cudaGetSymbolAddress((void**)&pw_as2,  w_as2);
    cudaGetSymbolAddress((void**)&pw_ih,   w_ih);
    cudaGetSymbolAddress((void**)&pw_hh,   w_hh);
    cudaGetSymbolAddress((void**)&pw_p1,   w_p1);
    cudaGetSymbolAddress((void**)&pw_p2,   w_p2);
    cudaGetSymbolAddress((void**)&pw_q1r,  w_q1r);
    cudaGetSymbolAddress((void**)&pw_q1o,  w_q1o);
    cudaGetSymbolAddress((void**)&pw_q2,   w_q2);

    float* out = (float*)d_out;
    const size_t BT = (size_t)BB * TT;
    float* o_pmean = out;
    float* o_pstd  = out + BT * SS;
    float* o_prior = out + 2 * BT * SS;
    float* o_bel   = out + 3 * BT * SS;
    float* o_qmean = out + 3 * BT * SS + BT * RR;
    float* o_qstd  = o_qmean + BT * SS;
    float* o_post  = o_qstd  + BT * SS;

    init_state<<<(BB * RR + 255) / 256, 256>>>(belief, posterior);

    auto prep = [](const float* src, int K, int N, int K3pad, int tr, __nv_bfloat16* dst) {
        int n = N * K3pad;
        prep_w<<<(n + 255) / 256, 256>>>(src, K, N, K3pad, tr, dst);
    };
    prep(W_as,              64,  512,  192, 1, pw_as1);
    prep(W_as + 64 * 512,   16,  512,   64, 1, pw_as2);
    prep(W_ih,             512, 1536, 1536, 0, pw_ih);
    prep(W_hh,             512, 1536, 1536, 0, pw_hh);
    prep(W_p1,             512,  512, 1536, 1, pw_p1);
    prep(W_p2,             512,  128, 1536, 1, pw_p2);
    prep(W_q1,             512,  512, 1536, 1, pw_q1r);
    prep(W_q1 + 512 * 512, 1024, 512, 3072, 1, pw_q1o);
    prep(W_q2,             512,  128, 1536, 1, pw_q2);

    {   // split obs + pad-split actions
        long total = (long)BT * EE;
        split_act<<<(unsigned)((total + 255) / 256), 256>>>(obs, pobs, total, EE);
        act_split_pad<<<(BB * TT * AA + 255) / 256, 256>>>(actions);
    }

    // act_pre = actions @ W_as2 + b_as   [B*T x 512]
    {
        GProb p = mkprob(pactpad, 64, 512, 1, pw_as2, 64,
                         b_as, nullptr, 0, pactpre, HH, nullptr, 0, 0);
        tgemm<<<dim3(8, (unsigned)(BT / 128)), 256>>>(p, p, 8);
    }
    // qpre = obs @ W_q1[R:,:] + b_q1     [B*T x 512]
    {
        GProb p = mkprob(pobs, 2 * EE, EE, 48, pw_q1o, 3072,
                         b_q1, nullptr, 0, pqpre, HH, nullptr, 0, 0);
        tgemm<<<dim3(8, (unsigned)(BT / 128)), 256>>>(p, p, 8);
    }

    for (int t = 0; t < TT; ++t) {
        // x = elu(post@W_as1 + act_pre_t) [8 tiles] || gh = bel@W_hh + b_hh [24 tiles]
        {
            GProb px_ = mkprob(pposts, 128, 64, 3, pw_as1, 192,
                               nullptr, pactpre + (size_t)t * HH, TT * HH,
                               nullptr, 0, pxs, HH, 1);
            GProb pgh_ = mkprob(pbels, 2 * RR, RR, 24, pw_hh, 1536,
                                b_hh, nullptr, 0, pgh, 3 * RR, nullptr, 0, 0);
            tgemm<<<dim3(32, 16), 256>>>(px_, pgh_, 8);
        }
        // gi = x @ W_ih + b_ih
        {
            GProb p = mkprob(pxs, 2 * HH, HH, 24, pw_ih, 1536,
                             b_ih, nullptr, 0, pgi, 3 * RR, nullptr, 0, 0);
            tgemm<<<dim3(24, 16), 256>>>(p, p, 24);
        }
        gru_kernel<<<(BB * RR) / 256, 256>>>(o_bel, t);
        // h2 = elu(bel @ W_q1[:R,:] + qpre_t)
        {
            GProb p = mkprob(pbels, 2 * RR, RR, 24, pw_q1r, 1536,
                             nullptr, pqpre + (size_t)t * HH, TT * HH,
                             nullptr, 0, ph2s, HH, 1);
            tgemm<<<dim3(8, 16), 256>>>(p, p, 8);
        }
        // q partials (split-K x4)
        {
            GProb p = mkprob(ph2s, 2 * HH, HH, 24, pw_q2, 1536,
                             nullptr, nullptr, 0, pqpart, 128, nullptr, 0, 0,
                             6, BB * 128);
            tgemm<<<dim3(2, 16, 4), 256>>>(p, p, 2);
        }
        dist_q_kernel<<<(BB * SS) / 256, 256>>>(noise_q, b_q2, o_qmean, o_qstd, o_post, t);
    }

    // deferred prior head over all B*T (h1_split aliases g_obs_split)
    {
        GProb p = mkprob(pbela, 2 * RR, RR, 24, pw_p1, 1536,
                         b_p1, nullptr, 0, nullptr, 0, pobs, HH, 1);
        tgemm<<<dim3(8, (unsigned)(BT / 128)), 256>>>(p, p, 8);
    }
    {
        GProb p = mkprob(pobs, 2 * HH, HH, 24, pw_p2, 1536,
                         b_p2, nullptr, 0, ppall, 2 * SS, nullptr, 0, 0);
        tgemm<<<dim3(2, (unsigned)(BT / 128)), 256>>>(p, p, 2);
    }
    dist_p_kernel<<<((unsigned)(BT * SS) + 255) / 256, 256>>>(noise_p, o_pmean, o_pstd, o_prior);
}